// round 6
// baseline (speedup 1.0000x reference)
#include <cuda_runtime.h>
#include <cstdint>

// ComparatorNBit: A,B float32 [N,32] in {0,1}, MSB first.
// Exact Boolean algebra => 32-bit unsigned compare of packed words.
//   d_out[0..N) = a_gt_b,  d_out[N..2N) = a_eq_b
//
// Persistent grid-stride version of the R4 winner:
//   - one wave: 148 SMs x 6 CTAs resident for the whole sweep (no wave
//     transitions, no late-wave stragglers)
//   - 8 lanes per row chunk; each 8-lane group handles 4 adjacent rows per
//     iteration: 8 front-batched LDG.128 per thread (MLP=8) in a 512B span
//   - nibble value via 3 FFMA (exact on {0,1} floats); cross-lane priority
//     via ballot + lsb isolate (lowest sub = most significant nibble)
//   - lane 0 stores float4 per output array
// Loop trip count is uniform across ALL threads (clamped loads, guarded
// stores), so full-mask ballots stay converged on the boundary iteration.

#define RPG 4   // rows per 8-lane group per iteration

__device__ __forceinline__ float nibf(const float4& v) {
    return fmaf(v.x, 8.0f, fmaf(v.y, 4.0f, fmaf(v.z, 2.0f, v.w)));
}

__global__ void __launch_bounds__(256, 6) comparator_nbit_kernel(
    const float4* __restrict__ A4,
    const float4* __restrict__ B4,
    float* __restrict__ out,
    int n, int total_groups, int iters)
{
    int tid0 = blockIdx.x * blockDim.x + threadIdx.x;
    int g0   = tid0 >> 3;                          // starting group id
    int sub  = tid0 & 7;                           // 16B chunk (0 = MSBs)
    int groups_per_iter = (gridDim.x * blockDim.x) >> 3;
    unsigned shift = (unsigned)(threadIdx.x & 24); // group's ballot byte

    for (int it = 0; it < iters; it++) {
        int g = g0 + it * groups_per_iter;
        int gc = min(g, total_groups - 1);         // clamp: keeps warp converged
        int r0 = gc * RPG;

        size_t base = (size_t)r0 * 8 + sub;
        float4 a[RPG], b[RPG];
        #pragma unroll
        for (int i = 0; i < RPG; i++) {
            a[i] = A4[base + 8 * i];
            b[i] = B4[base + 8 * i];
        }

        unsigned bal_ne[RPG], bal_gt[RPG];
        #pragma unroll
        for (int i = 0; i < RPG; i++) {
            float fa = nibf(a[i]);
            float fb = nibf(b[i]);
            bal_ne[i] = __ballot_sync(0xffffffffu, fa != fb);
            bal_gt[i] = __ballot_sync(0xffffffffu, fa >  fb);
        }

        if (sub == 0 && g < total_groups) {
            float gtv[RPG], eqv[RPG];
            #pragma unroll
            for (int i = 0; i < RPG; i++) {
                unsigned ne8 = (bal_ne[i] >> shift) & 0xFFu;
                unsigned lsb = ne8 & (0u - ne8);   // first differing nibble
                gtv[i] = ((bal_gt[i] >> shift) & lsb) ? 1.0f : 0.0f;
                eqv[i] = (ne8 == 0u) ? 1.0f : 0.0f;
            }
            if (r0 + RPG - 1 < n && (n & 3) == 0) {
                *(float4*)(out + r0)     = make_float4(gtv[0], gtv[1], gtv[2], gtv[3]);
                *(float4*)(out + n + r0) = make_float4(eqv[0], eqv[1], eqv[2], eqv[3]);
            } else {
                #pragma unroll
                for (int i = 0; i < RPG; i++)
                    if (r0 + i < n) {
                        out[r0 + i]     = gtv[i];
                        out[n + r0 + i] = eqv[i];
                    }
            }
        }
    }
}

extern "C" void kernel_launch(void* const* d_in, const int* in_sizes, int n_in,
                              void* d_out, int out_size)
{
    const float4* A4 = (const float4*)d_in[0];
    const float4* B4 = (const float4*)d_in[1];
    float* out = (float*)d_out;

    int n = in_sizes[0] / 32;                        // rows
    int total_groups = (n + RPG - 1) / RPG;

    const int block = 256;
    const int grid  = 148 * 6;                       // one resident wave
    int groups_per_iter = grid * block / 8;
    int iters = (total_groups + groups_per_iter - 1) / groups_per_iter;

    comparator_nbit_kernel<<<grid, block>>>(A4, B4, out, n, total_groups, iters);
}

// round 8
// speedup vs baseline: 1.0182x; 1.0182x over previous
#include <cuda_runtime.h>
#include <cstdint>

// ComparatorNBit: A,B float32 [N,32] in {0,1}, MSB first.
// Exact Boolean algebra => 32-bit unsigned compare of packed words.
//   d_out[0..N) = a_gt_b,  d_out[N..2N) = a_eq_b
//
// Persistent single-wave kernel with a 2-STAGE SOFTWARE PIPELINE:
// prefetch next tile's 8 LDG.128 (front-batched, independent) BEFORE doing
// the current tile's ballots/stores, so the per-warp memory queue never
// drains at loop boundaries (the flaw that sank the R6 plain persistent
// loop). 8 lanes per row chunk, 4 adjacent rows per group per iteration
// (MLP=8 in flight continuously, 512B span per thread). Nibble value via
// 3 FFMA (exact on {0,1}); cross-lane priority via ballot + lsb isolate.
// Clamped loads keep warps converged for full-mask ballots; stores guarded.

#define RPG 4   // rows per 8-lane group per iteration

__device__ __forceinline__ float nibf(const float4& v) {
    return fmaf(v.x, 8.0f, fmaf(v.y, 4.0f, fmaf(v.z, 2.0f, v.w)));
}

__global__ void __launch_bounds__(256, 3) comparator_nbit_kernel(
    const float4* __restrict__ A4,
    const float4* __restrict__ B4,
    float* __restrict__ out,
    int n, int total_groups, int iters)
{
    int tid0 = blockIdx.x * blockDim.x + threadIdx.x;
    int g0   = tid0 >> 3;                          // starting group id
    int sub  = tid0 & 7;                           // 16B chunk (0 = MSBs)
    int gpi  = (gridDim.x * blockDim.x) >> 3;      // groups per iteration
    unsigned shift = (unsigned)(threadIdx.x & 24); // group's ballot byte

    // ---- prologue: load tile for g0 ----
    float4 a[RPG], b[RPG], an[RPG], bn[RPG];
    {
        int gc = min(g0, total_groups - 1);
        size_t base = (size_t)gc * (RPG * 8) + sub;
        #pragma unroll
        for (int i = 0; i < RPG; i++) {
            a[i] = A4[base + 8 * i];
            b[i] = B4[base + 8 * i];
        }
    }

    int g = g0;
    for (int it = 0; it < iters; it++) {
        // ---- prefetch next tile (independent, issues before ballots) ----
        int gnext = g + gpi;
        {
            int gc = min(gnext, total_groups - 1);
            size_t base = (size_t)gc * (RPG * 8) + sub;
            #pragma unroll
            for (int i = 0; i < RPG; i++) {
                an[i] = A4[base + 8 * i];
                bn[i] = B4[base + 8 * i];
            }
        }

        // ---- process current tile ----
        unsigned bal_ne[RPG], bal_gt[RPG];
        #pragma unroll
        for (int i = 0; i < RPG; i++) {
            float fa = nibf(a[i]);
            float fb = nibf(b[i]);
            bal_ne[i] = __ballot_sync(0xffffffffu, fa != fb);
            bal_gt[i] = __ballot_sync(0xffffffffu, fa >  fb);
        }

        if (sub == 0 && g < total_groups) {
            int r0 = g * RPG;
            float gtv[RPG], eqv[RPG];
            #pragma unroll
            for (int i = 0; i < RPG; i++) {
                unsigned ne8 = (bal_ne[i] >> shift) & 0xFFu;
                unsigned lsb = ne8 & (0u - ne8);   // first differing nibble
                gtv[i] = ((bal_gt[i] >> shift) & lsb) ? 1.0f : 0.0f;
                eqv[i] = (ne8 == 0u) ? 1.0f : 0.0f;
            }
            if (r0 + RPG - 1 < n && (n & 3) == 0) {
                *(float4*)(out + r0)     = make_float4(gtv[0], gtv[1], gtv[2], gtv[3]);
                *(float4*)(out + n + r0) = make_float4(eqv[0], eqv[1], eqv[2], eqv[3]);
            } else {
                #pragma unroll
                for (int i = 0; i < RPG; i++)
                    if (r0 + i < n) {
                        out[r0 + i]     = gtv[i];
                        out[n + r0 + i] = eqv[i];
                    }
            }
        }

        // ---- rotate buffers ----
        #pragma unroll
        for (int i = 0; i < RPG; i++) { a[i] = an[i]; b[i] = bn[i]; }
        g = gnext;
    }
}

extern "C" void kernel_launch(void* const* d_in, const int* in_sizes, int n_in,
                              void* d_out, int out_size)
{
    const float4* A4 = (const float4*)d_in[0];
    const float4* B4 = (const float4*)d_in[1];
    float* out = (float*)d_out;

    int n = in_sizes[0] / 32;                        // rows
    int total_groups = (n + RPG - 1) / RPG;

    const int block = 256;
    const int grid  = 148 * 3;                       // one resident wave @ 3 CTAs/SM
    int gpi = grid * block / 8;
    int iters = (total_groups + gpi - 1) / gpi;

    comparator_nbit_kernel<<<grid, block>>>(A4, B4, out, n, total_groups, iters);
}

// round 10
// speedup vs baseline: 1.0446x; 1.0260x over previous
#include <cuda_runtime.h>
#include <cstdint>

// ComparatorNBit: A,B float32 [N,32] in {0,1}, MSB first.
// Exact Boolean algebra => 32-bit unsigned compare of packed words.
//   d_out[0..N) = a_gt_b,  d_out[N..2N) = a_eq_b
//
// Flat-grid R5 config (best: 78.8us, 6774 GB/s) with block=128 for better
// CTA packing: 74 regs -> 6 CTAs/SM resident (24 warps) vs 3 CTAs at
// block=256, i.e. ~26% more outstanding loads SM-wide at the same MLP=16
// per-thread depth. 8 lanes per row chunk, 8 adjacent rows per group:
// 16 front-batched LDG.128 per thread within a 1KB span; each warp reads
// contiguous 4KB per array. Nibble value via 3 FFMA (exact on {0,1});
// cross-lane priority via ballot + lsb isolate. Lane 0 stores 2x float4.

#define ROWS_PER_GROUP 8

__device__ __forceinline__ float nibf(const float4& v) {
    return fmaf(v.x, 8.0f, fmaf(v.y, 4.0f, fmaf(v.z, 2.0f, v.w)));
}

__global__ void __launch_bounds__(128) comparator_nbit_kernel(
    const float4* __restrict__ A4,
    const float4* __restrict__ B4,
    float* __restrict__ out,
    int n)
{
    int gid = blockIdx.x * blockDim.x + threadIdx.x;
    int g   = gid >> 3;                 // group: rows 8g .. 8g+7
    int sub = gid & 7;                  // 16B chunk within a row (0 = MSBs)
    int r0  = g << 3;
    if (r0 >= n) return;

    float4 a[ROWS_PER_GROUP], b[ROWS_PER_GROUP];
    if (r0 + ROWS_PER_GROUP - 1 < n) {
        size_t base = (size_t)r0 * 8 + sub;
        #pragma unroll
        for (int i = 0; i < ROWS_PER_GROUP; i++) {
            a[i] = A4[base + 8 * i];
            b[i] = B4[base + 8 * i];
        }
    } else {
        #pragma unroll
        for (int i = 0; i < ROWS_PER_GROUP; i++) {   // tail: clamp, extras discarded
            int r = min(r0 + i, n - 1);
            size_t idx = (size_t)r * 8 + sub;
            a[i] = A4[idx];
            b[i] = B4[idx];
        }
    }

    unsigned bal_ne[ROWS_PER_GROUP], bal_gt[ROWS_PER_GROUP];
    #pragma unroll
    for (int i = 0; i < ROWS_PER_GROUP; i++) {
        float fa = nibf(a[i]);
        float fb = nibf(b[i]);
        bal_ne[i] = __ballot_sync(0xffffffffu, fa != fb);
        bal_gt[i] = __ballot_sync(0xffffffffu, fa >  fb);
    }

    if (sub == 0) {
        unsigned shift = threadIdx.x & 24u;   // this group's byte of the ballot
        float gtv[ROWS_PER_GROUP], eqv[ROWS_PER_GROUP];
        #pragma unroll
        for (int i = 0; i < ROWS_PER_GROUP; i++) {
            unsigned ne8 = (bal_ne[i] >> shift) & 0xFFu;
            unsigned lsb = ne8 & (0u - ne8);  // first differing nibble (MSB-first)
            gtv[i] = ((bal_gt[i] >> shift) & lsb) ? 1.0f : 0.0f;
            eqv[i] = (ne8 == 0u) ? 1.0f : 0.0f;
        }
        if ((r0 + ROWS_PER_GROUP - 1 < n) && ((n & 7) == 0)) {
            *(float4*)(out + r0)         = make_float4(gtv[0], gtv[1], gtv[2], gtv[3]);
            *(float4*)(out + r0 + 4)     = make_float4(gtv[4], gtv[5], gtv[6], gtv[7]);
            *(float4*)(out + n + r0)     = make_float4(eqv[0], eqv[1], eqv[2], eqv[3]);
            *(float4*)(out + n + r0 + 4) = make_float4(eqv[4], eqv[5], eqv[6], eqv[7]);
        } else {
            #pragma unroll
            for (int i = 0; i < ROWS_PER_GROUP; i++)
                if (r0 + i < n) {
                    out[r0 + i]     = gtv[i];
                    out[n + r0 + i] = eqv[i];
                }
        }
    }
}

extern "C" void kernel_launch(void* const* d_in, const int* in_sizes, int n_in,
                              void* d_out, int out_size)
{
    const float4* A4 = (const float4*)d_in[0];
    const float4* B4 = (const float4*)d_in[1];
    float* out = (float*)d_out;

    int n = in_sizes[0] / 32;                            // rows
    long long groups = (n + ROWS_PER_GROUP - 1) / ROWS_PER_GROUP;
    long long total_threads = groups * 8;
    int block = 128;
    int grid = (int)((total_threads + block - 1) / block);

    comparator_nbit_kernel<<<grid, block>>>(A4, B4, out, n);
}

// round 12
// speedup vs baseline: 1.0493x; 1.0045x over previous
#include <cuda_runtime.h>
#include <cstdint>

// ComparatorNBit: A,B float32 [N,32] in {0,1}, MSB first.
// Exact Boolean algebra => 32-bit unsigned compare of packed words.
//   d_out[0..N) = a_gt_b,  d_out[N..2N) = a_eq_b
//
// R10 winner (block=128, 8 rows/group, MLP=16 front-batched LDG.128,
// FFMA nibble pack + ballot priority, float4 stores) with ONE change:
// __ldcs (evict-first streaming) on the 512MB read-once input stream to
// cut L2 thrash. Single-variable experiment vs R10.

#define ROWS_PER_GROUP 8

__device__ __forceinline__ float nibf(const float4& v) {
    return fmaf(v.x, 8.0f, fmaf(v.y, 4.0f, fmaf(v.z, 2.0f, v.w)));
}

__global__ void __launch_bounds__(128) comparator_nbit_kernel(
    const float4* __restrict__ A4,
    const float4* __restrict__ B4,
    float* __restrict__ out,
    int n)
{
    int gid = blockIdx.x * blockDim.x + threadIdx.x;
    int g   = gid >> 3;                 // group: rows 8g .. 8g+7
    int sub = gid & 7;                  // 16B chunk within a row (0 = MSBs)
    int r0  = g << 3;
    if (r0 >= n) return;

    float4 a[ROWS_PER_GROUP], b[ROWS_PER_GROUP];
    if (r0 + ROWS_PER_GROUP - 1 < n) {
        size_t base = (size_t)r0 * 8 + sub;
        #pragma unroll
        for (int i = 0; i < ROWS_PER_GROUP; i++) {
            a[i] = __ldcs(A4 + base + 8 * i);
            b[i] = __ldcs(B4 + base + 8 * i);
        }
    } else {
        #pragma unroll
        for (int i = 0; i < ROWS_PER_GROUP; i++) {   // tail: clamp, extras discarded
            int r = min(r0 + i, n - 1);
            size_t idx = (size_t)r * 8 + sub;
            a[i] = __ldcs(A4 + idx);
            b[i] = __ldcs(B4 + idx);
        }
    }

    unsigned bal_ne[ROWS_PER_GROUP], bal_gt[ROWS_PER_GROUP];
    #pragma unroll
    for (int i = 0; i < ROWS_PER_GROUP; i++) {
        float fa = nibf(a[i]);
        float fb = nibf(b[i]);
        bal_ne[i] = __ballot_sync(0xffffffffu, fa != fb);
        bal_gt[i] = __ballot_sync(0xffffffffu, fa >  fb);
    }

    if (sub == 0) {
        unsigned shift = threadIdx.x & 24u;   // this group's byte of the ballot
        float gtv[ROWS_PER_GROUP], eqv[ROWS_PER_GROUP];
        #pragma unroll
        for (int i = 0; i < ROWS_PER_GROUP; i++) {
            unsigned ne8 = (bal_ne[i] >> shift) & 0xFFu;
            unsigned lsb = ne8 & (0u - ne8);  // first differing nibble (MSB-first)
            gtv[i] = ((bal_gt[i] >> shift) & lsb) ? 1.0f : 0.0f;
            eqv[i] = (ne8 == 0u) ? 1.0f : 0.0f;
        }
        if ((r0 + ROWS_PER_GROUP - 1 < n) && ((n & 7) == 0)) {
            *(float4*)(out + r0)         = make_float4(gtv[0], gtv[1], gtv[2], gtv[3]);
            *(float4*)(out + r0 + 4)     = make_float4(gtv[4], gtv[5], gtv[6], gtv[7]);
            *(float4*)(out + n + r0)     = make_float4(eqv[0], eqv[1], eqv[2], eqv[3]);
            *(float4*)(out + n + r0 + 4) = make_float4(eqv[4], eqv[5], eqv[6], eqv[7]);
        } else {
            #pragma unroll
            for (int i = 0; i < ROWS_PER_GROUP; i++)
                if (r0 + i < n) {
                    out[r0 + i]     = gtv[i];
                    out[n + r0 + i] = eqv[i];
                }
        }
    }
}

extern "C" void kernel_launch(void* const* d_in, const int* in_sizes, int n_in,
                              void* d_out, int out_size)
{
    const float4* A4 = (const float4*)d_in[0];
    const float4* B4 = (const float4*)d_in[1];
    float* out = (float*)d_out;

    int n = in_sizes[0] / 32;                            // rows
    long long groups = (n + ROWS_PER_GROUP - 1) / ROWS_PER_GROUP;
    long long total_threads = groups * 8;
    int block = 128;
    int grid = (int)((total_threads + block - 1) / block);

    comparator_nbit_kernel<<<grid, block>>>(A4, B4, out, n);
}